// round 16
// baseline (speedup 1.0000x reference)
#include <cuda_runtime.h>
#include <cuda_fp16.h>
#include <math.h>
#include <stdint.h>

#define BATCH 8192
#define DIM   512
#define MEM   1000
#define MEMP  1024
#define HEADS 8
#define DH    64

// ==================== helpers ====================
__device__ __forceinline__ uint32_t smem_u32(const void* p) {
    uint32_t a;
    asm("{ .reg .u64 t; cvta.to.shared.u64 t, %1; cvt.u32.u64 %0, t; }" : "=r"(a) : "l"(p));
    return a;
}
__device__ __forceinline__ void mma_f16(float* c, uint32_t a0, uint32_t a1,
                                        uint32_t a2, uint32_t a3,
                                        uint32_t b0, uint32_t b1) {
    asm volatile(
        "mma.sync.aligned.m16n8k16.row.col.f32.f16.f16.f32 "
        "{%0,%1,%2,%3}, {%4,%5,%6,%7}, {%8,%9}, {%0,%1,%2,%3};"
        : "+f"(c[0]), "+f"(c[1]), "+f"(c[2]), "+f"(c[3])
        : "r"(a0), "r"(a1), "r"(a2), "r"(a3), "r"(b0), "r"(b1));
}
__device__ __forceinline__ void ldsm_x4(uint32_t* r, uint32_t addr) {
    asm volatile("ldmatrix.sync.aligned.m8n8.x4.shared.b16 {%0,%1,%2,%3}, [%4];"
        : "=r"(r[0]), "=r"(r[1]), "=r"(r[2]), "=r"(r[3]) : "r"(addr));
}
__device__ __forceinline__ void ldsm_x2(uint32_t& r0, uint32_t& r1, uint32_t addr) {
    asm volatile("ldmatrix.sync.aligned.m8n8.x2.shared.b16 {%0,%1}, [%2];"
        : "=r"(r0), "=r"(r1) : "r"(addr));
}
__device__ __forceinline__ void cp_async16(uint32_t dst, const void* src, int srcsize) {
    asm volatile("cp.async.cg.shared.global [%0], [%1], 16, %2;"
                 :: "r"(dst), "l"(src), "r"(srcsize));
}
#define CP_COMMIT() asm volatile("cp.async.commit_group;" ::: "memory")
#define CP_WAIT(N)  asm volatile("cp.async.wait_group %0;" :: "n"(N) : "memory")

// ==================== scratch ====================
__device__ float  g_h[BATCH*DIM];
__device__ float  g_enc[BATCH*DIM];
__device__ __half g_hn_h[BATCH*DIM];
__device__ __half g_enc_h[BATCH*DIM];
__device__ __half g_q_h[BATCH*DIM];       // pre-scaled by 0.125
__device__ __half g_ctx_h[BATCH*DIM];
__device__ __half g_fused_h[BATCH*DIM];
__device__ __half g_ns_h[BATCH*DIM];
__device__ __half g_k_h[MEMP*DIM];
__device__ __half g_vt_h[DIM*MEMP];       // V^T: [d][m]
__device__ __half g_obs_h[BATCH*DIM];
__device__ __half g_ego_h[BATCH*16];
__device__ __half g_wm_h[MEMP*DIM];
__device__ __half g_w2t_h[DIM*DIM];       // enc_w2 transposed
__device__ __half g_wc_h[DIM*DIM];        // Wc = Wq * W2 (composite)
__device__ float  g_bc[DIM];              // bc = Wq*b2 + bq
__device__ float  g_zero[DIM];            // zero bias
#define W_ENC1 0
#define W_ENC2 262144
#define W_WQ   524288
#define W_WK   786432
#define W_WV   1048576
#define W_WO   1310720
#define W_TR1  1572864
#define W_TR2  1843200
#define W_Q1   2105344
#define W_TOT  2170880
__device__ __half g_w_h[W_TOT];
__device__ int    g_midx[BATCH];
__device__ int    g_mcount;

// ==================== prep: fp32 -> fp16 ====================
struct PrepArgs {
    const float* src[12];
    __half*      dst[12];
    int          n4[12];
};
__global__ void __launch_bounds__(256) prep_kernel(PrepArgs p) {
    int seg = blockIdx.y;
    int n4 = p.n4[seg];
    const float4* s = (const float4*)p.src[seg];
    for (int i = blockIdx.x * 256 + threadIdx.x; i < n4; i += gridDim.x * 256) {
        float4 v = s[i];
        __half2 lo = __floats2half2_rn(v.x, v.y);
        __half2 hi = __floats2half2_rn(v.z, v.w);
        uint2 pk;
        pk.x = *(uint32_t*)&lo; pk.y = *(uint32_t*)&hi;
        *(uint2*)(p.dst[seg] + (size_t)i * 4) = pk;
    }
}

// transpose 512x512 fp32 -> fp16: dst[k][i] = src[i][k]
__global__ void __launch_bounds__(256) transpose_kernel(
    const float* __restrict__ src, __half* __restrict__ dst)
{
    __shared__ float tile[32][33];
    int x = blockIdx.x * 32 + threadIdx.x;
    int y0 = blockIdx.y * 32 + threadIdx.y;
    #pragma unroll
    for (int j = 0; j < 4; ++j)
        tile[threadIdx.y + j * 8][threadIdx.x] = src[(size_t)(y0 + j * 8) * 512 + x];
    __syncthreads();
    int xo = blockIdx.y * 32 + threadIdx.x;
    int yo = blockIdx.x * 32 + threadIdx.y;
    #pragma unroll
    for (int j = 0; j < 4; ++j)
        dst[(size_t)(yo + j * 8) * 512 + xo] =
            __float2half_rn(tile[threadIdx.x][threadIdx.y + j * 8]);
}

// bc[i] = bq[i] + sum_k wq[i,k] * b2[k]   (fp32)
__global__ void __launch_bounds__(256) bc_kernel(
    const float* __restrict__ wq, const float* __restrict__ b2,
    const float* __restrict__ bq, float* __restrict__ bc)
{
    int i = blockIdx.x * 256 + threadIdx.x;
    float s = bq[i];
    const float* wr = wq + (size_t)i * 512;
    #pragma unroll 8
    for (int k = 0; k < 512; ++k) s += wr[k] * b2[k];
    bc[i] = s;
}

// ==================== fp16 mma GEMM, 256 thr, NT=128, BK=64, 2 CTA/SM ========
// EPI: 1 relu->f32, 2 fuse->f16, 3 quality, 4 f16, 5 dual f32+f16,
//      6 f16 scaled 0.125, 7 f16 row-bias (V^T)
#define GSH 72
#define NT  128
#define NF  4
template<int EPI>
__global__ void __launch_bounds__(256, 2) gemm_mma(
    const __half* __restrict__ A, const __half* __restrict__ A2,
    const __half* __restrict__ W, const float* __restrict__ bias,
    const float* __restrict__ F, const float* __restrict__ w2,
    const float* __restrict__ b2, void* __restrict__ Cv, void* __restrict__ C2v,
    int Mrows, int Kw, int Ktiles, int ldc)
{
    constexpr int ASZ = 128 * GSH;
    constexpr int WSZ = NT * GSH;
    extern __shared__ __half smh[];
    __half* Ah = smh;
    __half* Wh = smh + 3 * ASZ;
    const uint32_t sA = smem_u32(Ah);
    const uint32_t sW = smem_u32(Wh);

    const int tid = threadIdx.x;
    const int wid = tid >> 5, lane = tid & 31;
    const int g = lane >> 2, t = lane & 3;
    const int wm = wid & 1, wn = wid >> 1;
    const int row0 = blockIdx.y * 128;
    const int col0 = blockIdx.x * NT;

    const int lane16 = lane & 15, laneHi = lane >> 4;
    const int lane8  = lane & 7,  laneK  = (lane >> 3) & 1;
    uint32_t aoff[4], boff[NF];
    #pragma unroll
    for (int mf = 0; mf < 4; ++mf)
        aoff[mf] = ((wm * 64 + mf * 16 + lane16) * GSH + laneHi * 8) * 2;
    #pragma unroll
    for (int nf = 0; nf < NF; ++nf)
        boff[nf] = ((wn * (NT / 4) + nf * 8 + lane8) * GSH + laneK * 8) * 2;

    float acc[4][NF][4];
    #pragma unroll
    for (int mf = 0; mf < 4; ++mf)
        #pragma unroll
        for (int nf = 0; nf < NF; ++nf)
            #pragma unroll
            for (int c = 0; c < 4; ++c) acc[mf][nf][c] = 0.f;

    auto load_chunk = [&](int ct, int buf) {
        const int kbase = ct * 64;
        #pragma unroll
        for (int it = 0; it < 8; ++it) {
            int vid = tid + it * 256;
            if (vid < 1024) {
                int r = vid >> 3, q = vid & 7;
                int kel = kbase + q * 8;
                int grow = row0 + r;
                const __half* src = A;
                int sz = 0;
                if (grow < Mrows) {
                    if (kel < 512) { src = A + (size_t)grow * 512 + kel; sz = 16; }
                    else if (A2 != nullptr && kel < 528) {
                        src = A2 + (size_t)grow * 16 + (kel - 512); sz = 16;
                    }
                }
                cp_async16(sA + (buf * ASZ + r * GSH + q * 8) * 2, src, sz);
            } else {
                int vid2 = vid - 1024;
                int r = vid2 >> 3, q = vid2 & 7;
                int kel = kbase + q * 8;
                const __half* src = W + (size_t)(col0 + r) * Kw + kel;
                int sz = (kel < Kw) ? 16 : 0;
                cp_async16(sW + (buf * WSZ + r * GSH + q * 8) * 2, src, sz);
            }
        }
        CP_COMMIT();
    };

    load_chunk(0, 0);
    if (Ktiles > 1) load_chunk(1, 1);

    for (int ct = 0; ct < Ktiles; ++ct) {
        const int buf = ct % 3;
        if (ct + 2 < Ktiles) load_chunk(ct + 2, (ct + 2) % 3);
        if (ct + 2 < Ktiles)      { CP_WAIT(2); }
        else if (ct + 1 < Ktiles) { CP_WAIT(1); }
        else                      { CP_WAIT(0); }
        __syncthreads();

        const uint32_t abase = sA + buf * ASZ * 2;
        const uint32_t bbase = sW + buf * WSZ * 2;
        #pragma unroll
        for (int ks = 0; ks < 4; ++ks) {
            const uint32_t kb = ks * 32;
            uint32_t af[4][4];
            #pragma unroll
            for (int mf = 0; mf < 4; ++mf)
                ldsm_x4(af[mf], abase + aoff[mf] + kb);
            #pragma unroll
            for (int nf = 0; nf < NF; ++nf) {
                uint32_t b0, b1;
                ldsm_x2(b0, b1, bbase + boff[nf] + kb);
                #pragma unroll
                for (int mf = 0; mf < 4; ++mf)
                    mma_f16(acc[mf][nf], af[mf][0], af[mf][1], af[mf][2], af[mf][3], b0, b1);
            }
        }
        __syncthreads();
    }

    if (EPI != 3) {
        #pragma unroll
        for (int mf = 0; mf < 4; ++mf) {
            #pragma unroll
            for (int r01 = 0; r01 < 2; ++r01) {
                int grow = row0 + wm * 64 + mf * 16 + g + r01 * 8;
                if (grow >= Mrows) continue;
                #pragma unroll
                for (int nf = 0; nf < NF; ++nf) {
                    int gcol = col0 + wn * (NT / 4) + nf * 8 + 2 * t;
                    float b0 = (EPI == 7) ? bias[grow] : bias[gcol];
                    float b1 = (EPI == 7) ? bias[grow] : bias[gcol + 1];
                    float v0 = acc[mf][nf][r01 * 2 + 0] + b0;
                    float v1 = acc[mf][nf][r01 * 2 + 1] + b1;
                    if (EPI == 1) { v0 = fmaxf(v0, 0.f); v1 = fmaxf(v1, 0.f); }
                    else if (EPI == 2) {
                        const float* fp = F + (size_t)grow * 512 + gcol;
                        v0 = 0.7f * fp[0] + 0.3f * v0;
                        v1 = 0.7f * fp[1] + 0.3f * v1;
                    } else if (EPI == 6) { v0 *= 0.125f; v1 *= 0.125f; }
                    size_t off = (size_t)grow * ldc + gcol;
                    if (EPI == 1) {
                        *(float2*)((float*)Cv + off) = make_float2(v0, v1);
                    } else if (EPI == 5) {
                        *(float2*)((float*)Cv + off) = make_float2(v0, v1);
                        __half2 hv = __floats2half2_rn(v0, v1);
                        *(__half2*)((__half*)C2v + off) = hv;
                    } else {
                        __half2 hv = __floats2half2_rn(v0, v1);
                        *(__half2*)((__half*)Cv + off) = hv;
                    }
                }
            }
        }
    } else {
        // quality head (NT=128, col0=0): sigmoid(b2 + sum relu(acc+b1)*w2)
        float* qpart = (float*)smh;
        __syncthreads();
        #pragma unroll
        for (int mf = 0; mf < 4; ++mf) {
            #pragma unroll
            for (int r01 = 0; r01 < 2; ++r01) {
                float s = 0.f;
                #pragma unroll
                for (int nf = 0; nf < NF; ++nf) {
                    int c = wn * (NT / 4) + nf * 8 + 2 * t;
                    float h0 = fmaxf(acc[mf][nf][r01 * 2 + 0] + bias[c], 0.f);
                    float h1 = fmaxf(acc[mf][nf][r01 * 2 + 1] + bias[c + 1], 0.f);
                    s += h0 * w2[c] + h1 * w2[c + 1];
                }
                int rl = wm * 64 + mf * 16 + r01 * 8 + g;
                qpart[rl * 17 + wn * 4 + t] = s;
            }
        }
        __syncthreads();
        if (tid < 128) {
            float s = b2[0];
            #pragma unroll
            for (int i = 0; i < 16; ++i) s += qpart[tid * 17 + i];
            ((float*)Cv)[row0 + tid] = 1.f / (1.f + expf(-s));
        }
    }
}
#define GEMM_SMEM ((3 * 128 * GSH + 3 * NT * GSH) * 2)

// ==================== fp16 mma flash attention ==============================
#define AS 72
#define KVSZ (64 * AS)
#define ATT_SMEM ((128*AS + 2*KVSZ + 2*KVSZ) * 2)
__global__ void __launch_bounds__(256, 2) attn_mma(
    const __half* __restrict__ Q, const __half* __restrict__ Kb,
    const __half* __restrict__ Vt, __half* __restrict__ ctx)
{
    extern __shared__ __half smh[];
    __half* Qs = smh;
    __half* Ks = Qs + 128 * AS;
    __half* Vs = Ks + 2 * KVSZ;
    const uint32_t sQ = smem_u32(Qs);
    const uint32_t sK = smem_u32(Ks);
    const uint32_t sV = smem_u32(Vs);

    const int h = blockIdx.x;
    const int b0 = blockIdx.y * 128;
    const int tid = threadIdx.x;
    const int wid = tid >> 5, lane = tid & 31;
    const int g = lane >> 2, t = lane & 3;
    const int qr = wid * 16;

    const int lane16 = lane & 15, laneHi = lane >> 4;
    const int lane8  = lane & 7,  laneK  = (lane >> 3) & 1;
    uint32_t kvoff[8];
    #pragma unroll
    for (int nf = 0; nf < 8; ++nf)
        kvoff[nf] = ((nf * 8 + lane8) * AS + laneK * 8) * 2;

    auto load_kv = [&](int m0, int buf) {
        #pragma unroll
        for (int it = 0; it < 4; ++it) {
            int vid = tid + it * 256;
            if (vid < 512) {
                int r = vid >> 3, q = vid & 7;
                int gm = m0 + r;
                int sz = (gm < MEM) ? 16 : 0;
                cp_async16(sK + (buf * KVSZ + r * AS + q * 8) * 2,
                           Kb + (size_t)gm * 512 + h * 64 + q * 8, sz);
            } else {
                int vid2 = vid - 512;
                int r = vid2 >> 3, q = vid2 & 7;
                cp_async16(sV + (buf * KVSZ + r * AS + q * 8) * 2,
                           Vt + (size_t)(h * 64 + r) * MEMP + m0 + q * 8, 16);
            }
        }
        CP_COMMIT();
    };

    load_kv(0, 0);

    #pragma unroll
    for (int it = 0; it < 4; ++it) {
        int vid = tid + it * 256;
        int r = vid >> 3, q = vid & 7;
        uint4 v = *(const uint4*)(Q + (size_t)(b0 + r) * 512 + h * 64 + q * 8);
        *(uint4*)(Qs + r * AS + q * 8) = v;
    }
    __syncthreads();
    uint32_t qa[4][4];
    #pragma unroll
    for (int ks = 0; ks < 4; ++ks)
        ldsm_x4(qa[ks], sQ + ((qr + lane16) * AS + ks * 16 + laneHi * 8) * 2);

    float oacc[8][4];
    float rsum[2] = {0.f, 0.f};
    #pragma unroll
    for (int nf = 0; nf < 8; ++nf)
        #pragma unroll
        for (int c = 0; c < 4; ++c) oacc[nf][c] = 0.f;

    for (int ci = 0; ci < MEMP / 64; ++ci) {
        const int m0 = ci * 64;
        const int buf = ci & 1;
        if (ci + 1 < MEMP / 64) { load_kv(m0 + 64, buf ^ 1); CP_WAIT(1); }
        else                    { CP_WAIT(0); }
        __syncthreads();

        const uint32_t kbase = sK + buf * KVSZ * 2;
        const uint32_t vbase = sV + buf * KVSZ * 2;

        float sacc[8][4];
        #pragma unroll
        for (int nf = 0; nf < 8; ++nf)
            #pragma unroll
            for (int c = 0; c < 4; ++c) sacc[nf][c] = 0.f;
        #pragma unroll
        for (int ks = 0; ks < 4; ++ks) {
            const uint32_t kb = ks * 32;
            #pragma unroll
            for (int nf = 0; nf < 8; ++nf) {
                uint32_t b0, b1;
                ldsm_x2(b0, b1, kbase + kvoff[nf] + kb);
                mma_f16(sacc[nf], qa[ks][0], qa[ks][1], qa[ks][2], qa[ks][3], b0, b1);
            }
        }

        uint32_t pa[4][4];
        #pragma unroll
        for (int nf = 0; nf < 8; ++nf) {
            float p0 = 0.f, p1 = 0.f, p2 = 0.f, p3 = 0.f;
            bool in0 = (m0 + nf * 8 + 2 * t) < MEM;
            bool in1 = (m0 + nf * 8 + 2 * t + 1) < MEM;
            if (in0) { p0 = __expf(sacc[nf][0]); p2 = __expf(sacc[nf][2]); }
            if (in1) { p1 = __expf(sacc[nf][1]); p3 = __expf(sacc[nf][3]); }
            rsum[0] += p0 + p1;
            rsum[1] += p2 + p3;
            __half2 lo = __floats2half2_rn(p0, p1);
            __half2 hi = __floats2half2_rn(p2, p3);
            pa[nf >> 1][(nf & 1) * 2 + 0] = *(uint32_t*)&lo;
            pa[nf >> 1][(nf & 1) * 2 + 1] = *(uint32_t*)&hi;
        }

        #pragma unroll
        for (int ks = 0; ks < 4; ++ks) {
            const uint32_t kb = ks * 32;
            #pragma unroll
            for (int nf = 0; nf < 8; ++nf) {
                uint32_t b0, b1;
                ldsm_x2(b0, b1, vbase + kvoff[nf] + kb);
                mma_f16(oacc[nf], pa[ks][0], pa[ks][1], pa[ks][2], pa[ks][3], b0, b1);
            }
        }
        __syncthreads();
    }

    #pragma unroll
    for (int r01 = 0; r01 < 2; ++r01) {
        rsum[r01] += __shfl_xor_sync(0xffffffffu, rsum[r01], 1);
        rsum[r01] += __shfl_xor_sync(0xffffffffu, rsum[r01], 2);
    }

    #pragma unroll
    for (int r01 = 0; r01 < 2; ++r01) {
        float inv = 1.f / rsum[r01];
        int grow = b0 + qr + g + r01 * 8;
        #pragma unroll
        for (int nf = 0; nf < 8; ++nf) {
            __half2 o = __floats2half2_rn(oacc[nf][r01 * 2 + 0] * inv,
                                          oacc[nf][r01 * 2 + 1] * inv);
            *(__half2*)(ctx + (size_t)grow * 512 + h * 64 + nf * 8 + 2 * t) = o;
        }
    }
}

// ==================== LayerNorm: warp-per-row, fp32 in, fp16 out =============
__global__ void __launch_bounds__(256) ln_kernel(
    const float* __restrict__ x, const float* __restrict__ g,
    const float* __restrict__ b, __half* __restrict__ y)
{
    const int warp = threadIdx.x >> 5, lane = threadIdx.x & 31;
    const int row = blockIdx.x * 8 + warp;
    const float* xr = x + (size_t)row * 512;

    float4 v[4];
    #pragma unroll
    for (int i = 0; i < 4; ++i)
        v[i] = *(const float4*)(xr + i * 128 + lane * 4);

    float s = 0.f;
    #pragma unroll
    for (int i = 0; i < 4; ++i) s += v[i].x + v[i].y + v[i].z + v[i].w;
    #pragma unroll
    for (int o = 16; o > 0; o >>= 1) s += __shfl_xor_sync(0xffffffffu, s, o);
    float mean = s * (1.f / 512.f);

    float ss = 0.f;
    #pragma unroll
    for (int i = 0; i < 4; ++i) {
        v[i].x -= mean; v[i].y -= mean; v[i].z -= mean; v[i].w -= mean;
        ss += v[i].x * v[i].x + v[i].y * v[i].y + v[i].z * v[i].z + v[i].w * v[i].w;
    }
    #pragma unroll
    for (int o = 16; o > 0; o >>= 1) ss += __shfl_xor_sync(0xffffffffu, ss, o);
    float inv = rsqrtf(ss * (1.f / 512.f) + 1e-5f);

    #pragma unroll
    for (int i = 0; i < 4; ++i) {
        float4 gg = *(const float4*)(g + i * 128 + lane * 4);
        float4 bb = *(const float4*)(b + i * 128 + lane * 4);
        __half2 lo = __floats2half2_rn(v[i].x * inv * gg.x + bb.x,
                                       v[i].y * inv * gg.y + bb.y);
        __half2 hi = __floats2half2_rn(v[i].z * inv * gg.z + bb.z,
                                       v[i].w * inv * gg.w + bb.w);
        uint2 pk; pk.x = *(uint32_t*)&lo; pk.y = *(uint32_t*)&hi;
        *(uint2*)(y + (size_t)row * 512 + i * 128 + lane * 4) = pk;
    }
}

// ==================== mask compaction + memory EMA ====================
__global__ void __launch_bounds__(256) compact_kernel(
    const float* __restrict__ quality, int* __restrict__ midx, int* __restrict__ mcount)
{
    const int tid = threadIdx.x;
    const int base = tid * 32;
    int cnt = 0;
    for (int i = 0; i < 32; ++i) cnt += (quality[base + i] > 0.7f) ? 1 : 0;
    __shared__ int sc[256];
    __shared__ int offs[256];
    sc[tid] = cnt;
    __syncthreads();
    if (tid == 0) {
        int run = 0;
        for (int t = 0; t < 256; ++t) { offs[t] = run; run += sc[t]; }
        *mcount = run;
    }
    __syncthreads();
    int o = offs[tid];
    for (int i = 0; i < 32; ++i)
        if (quality[base + i] > 0.7f) midx[o++] = base + i;
}

__global__ void __launch_bounds__(128) memupd_kernel(
    const float* __restrict__ wm, const float* __restrict__ ns,
    const int* __restrict__ upd, const int* __restrict__ midx,
    const int* __restrict__ mcount, float* __restrict__ outmem)
{
    const int m = blockIdx.x;
    const int d = threadIdx.x * 4;
    float4 v = *(const float4*)(wm + (size_t)m * 512 + d);
    const int cnt = *mcount;
    for (int jj = 0; jj < cnt; ++jj) {
        int i = midx[jj];
        if (upd[i] == m) {
            float4 s = *(const float4*)(ns + (size_t)i * 512 + d);
            v.x = 0.9f * v.x + 0.1f * s.x;
            v.y = 0.9f * v.y + 0.1f * s.y;
            v.z = 0.9f * v.z + 0.1f * s.z;
            v.w = 0.9f * v.w + 0.1f * s.w;
        }
    }
    *(float4*)(outmem + (size_t)m * 512 + d) = v;
}

// ==================== host launcher ====================
extern "C" void kernel_launch(void* const* d_in, const int* in_sizes, int n_in,
                              void* d_out, int out_size)
{
    const float* obs    = (const float*)d_in[0];
    const float* ego    = (const float*)d_in[1];
    const float* wm     = (const float*)d_in[2];
    const float* enc_w1 = (const float*)d_in[3];
    const float* enc_b1 = (const float*)d_in[4];
    const float* enc_g  = (const float*)d_in[5];
    const float* enc_be = (const float*)d_in[6];
    const float* enc_w2 = (const float*)d_in[7];
    const float* enc_b2 = (const float*)d_in[8];
    const float* wq     = (const float*)d_in[9];
    const float* bq     = (const float*)d_in[10];
    const float* wk     = (const float*)d_in[11];
    const float* bk     = (const float*)d_in[12];
    const float* wv     = (const float*)d_in[13];
    const float* bv     = (const float*)d_in[14];
    const float* wo     = (const float*)d_in[15];
    const float* bo     = (const float*)d_in[16];
    const float* tr_w1  = (const float*)d_in[17];
    const float* tr_b1  = (const float*)d_in[18];
    const float* tr_g   = (const float*)d_in[19];
    const float* tr_be  = (const float*)d_in[20];
    const float* tr_w2  = (const float*)d_in[21];
    const float* tr_b2  = (const float*)d_in[22];
    const float* q_w1   = (const float*)d_in[23];
    const float* q_b1   = (const float*)d_in[24];
    const float* q_w2   = (const float*)d_in[25];
    const float* q_b2   = (const float*)d_in[26];
    const int*   uidx   = (const int*)d_in[27];

    float* out        = (float*)d_out;
    float* next_state = out;
    float* quality    = out + (size_t)BATCH * DIM;
    float* outmem     = quality + BATCH;

    float *h, *enc, *bc, *zero;
    __half *hn_h, *enc_h, *q_h, *ctx_h, *fused_h, *ns_h, *k_h, *vt_h;
    __half *obs_h, *ego_h, *wm_h, *w_h, *w2t_h, *wc_h;
    int *midx, *mcount;
    cudaGetSymbolAddress((void**)&h,      g_h);
    cudaGetSymbolAddress((void**)&enc,    g_enc);
    cudaGetSymbolAddress((void**)&hn_h,   g_hn_h);
    cudaGetSymbolAddress((void**)&enc_h,  g_enc_h);
    cudaGetSymbolAddress((void**)&q_h,    g_q_h);
    cudaGetSymbolAddress((void**)&ctx_h,  g_ctx_h);
    cudaGetSymbolAddress((void**)&fused_h,g_fused_h);
    cudaGetSymbolAddress((void**)&ns_h,   g_ns_h);
    cudaGetSymbolAddress((void**)&k_h,    g_k_h);
    cudaGetSymbolAddress((void**)&vt_h,   g_vt_h);
    cudaGetSymbolAddress((void**)&obs_h,  g_obs_h);
    cudaGetSymbolAddress((void**)&ego_h,  g_ego_h);
    cudaGetSymbolAddress((void**)&wm_h,   g_wm_h);
    cudaGetSymbolAddress((void**)&w_h,    g_w_h);
    cudaGetSymbolAddress((void**)&w2t_h,  g_w2t_h);
    cudaGetSymbolAddress((void**)&wc_h,   g_wc_h);
    cudaGetSymbolAddress((void**)&bc,     g_bc);
    cudaGetSymbolAddress((void**)&zero,   g_zero);
    cudaGetSymbolAddress((void**)&midx,   g_midx);
    cudaGetSymbolAddress((void**)&mcount, g_mcount);

    cudaFuncSetAttribute(gemm_mma<1>, cudaFuncAttributeMaxDynamicSharedMemorySize, GEMM_SMEM);
    cudaFuncSetAttribute(gemm_mma<2>, cudaFuncAttributeMaxDynamicSharedMemorySize, GEMM_SMEM);
    cudaFuncSetAttribute(gemm_mma<3>, cudaFuncAttributeMaxDynamicSharedMemorySize, GEMM_SMEM);
    cudaFuncSetAttribute(gemm_mma<4>, cudaFuncAttributeMaxDynamicSharedMemorySize, GEMM_SMEM);
    cudaFuncSetAttribute(gemm_mma<5>, cudaFuncAttributeMaxDynamicSharedMemorySize, GEMM_SMEM);
    cudaFuncSetAttribute(gemm_mma<6>, cudaFuncAttributeMaxDynamicSharedMemorySize, GEMM_SMEM);
    cudaFuncSetAttribute(gemm_mma<7>, cudaFuncAttributeMaxDynamicSharedMemorySize, GEMM_SMEM);
    cudaFuncSetAttribute(attn_mma,    cudaFuncAttributeMaxDynamicSharedMemorySize, ATT_SMEM);

    static cudaStream_t s1 = nullptr;
    static cudaEvent_t  eP = nullptr, eLN = nullptr, eQ = nullptr;
    if (s1 == nullptr) {
        cudaStreamCreateWithFlags(&s1, cudaStreamNonBlocking);
        cudaEventCreateWithFlags(&eP,  cudaEventDisableTiming);
        cudaEventCreateWithFlags(&eLN, cudaEventDisableTiming);
        cudaEventCreateWithFlags(&eQ,  cudaEventDisableTiming);
    }

    // ---- prep: fp32 -> fp16 ----
    PrepArgs pa;
    const float* srcs[12] = {obs, ego, wm, enc_w1, enc_w2, wq, wk, wv, wo, tr_w1, tr_w2, q_w1};
    __half* dsts[12] = {obs_h, ego_h, wm_h,
                        w_h + W_ENC1, w_h + W_ENC2, w_h + W_WQ, w_h + W_WK, w_h + W_WV,
                        w_h + W_WO, w_h + W_TR1, w_h + W_TR2, w_h + W_Q1};
    int n4s[12] = {BATCH*DIM/4, BATCH*16/4, MEM*DIM/4,
                   262144/4, 262144/4, 262144/4, 262144/4, 262144/4,
                   262144/4, 270336/4, 262144/4, 65536/4};
    for (int i = 0; i < 12; ++i) { pa.src[i] = srcs[i]; pa.dst[i] = dsts[i]; pa.n4[i] = n4s[i]; }
    prep_kernel<<<dim3(512, 12), 256>>>(pa);

    dim3 gBig(4, 64), gK(4, 8), gVt(8, 4), gWc(4, 4), gQual(1, 64);

    // ---- fork: side stream (depends only on prep) ----
    cudaEventRecord(eP, 0);
    cudaStreamWaitEvent(s1, eP, 0);
    gemm_mma<4><<<gK, 256, GEMM_SMEM, s1>>>(wm_h, nullptr, w_h + W_WK, bk,
        nullptr, nullptr, nullptr, k_h, nullptr, MEM, 512, 8, 512);
    gemm_mma<7><<<gVt, 256, GEMM_SMEM, s1>>>(w_h + W_WV, nullptr, wm_h, bv,
        nullptr, nullptr, nullptr, vt_h, nullptr, 512, 512, 8, MEMP);
    transpose_kernel<<<dim3(16, 16), dim3(32, 8), 0, s1>>>(enc_w2, w2t_h);
    bc_kernel<<<2, 256, 0, s1>>>(wq, enc_b2, bq, bc);
    // Wc = Wq * W2  (A = wq_h, W = W2^T)
    gemm_mma<4><<<gWc, 256, GEMM_SMEM, s1>>>(w_h + W_WQ, nullptr, w2t_h, zero,
        nullptr, nullptr, nullptr, wc_h, nullptr, 512, 512, 8, 512);

    // ---- main chain ----
    gemm_mma<1><<<gBig, 256, GEMM_SMEM>>>(obs_h, nullptr, w_h + W_ENC1, enc_b1,
        nullptr, nullptr, nullptr, h, nullptr, BATCH, 512, 8, 512);
    ln_kernel<<<BATCH/8, 256>>>(h, enc_g, enc_be, hn_h);
    cudaEventRecord(eLN, 0);

    // side stream: Qproj from hn via composite weight (concurrent with enc2)
    cudaStreamWaitEvent(s1, eLN, 0);
    gemm_mma<6><<<gBig, 256, GEMM_SMEM, s1>>>(hn_h, nullptr, wc_h, bc,
        nullptr, nullptr, nullptr, q_h, nullptr, BATCH, 512, 8, 512);
    cudaEventRecord(eQ, s1);

    gemm_mma<5><<<gBig, 256, GEMM_SMEM>>>(hn_h, nullptr, w_h + W_ENC2, enc_b2,
        nullptr, nullptr, nullptr, enc, enc_h, BATCH, 512, 8, 512);
    // join q (covers K/Vt transitively on in-order s1)
    cudaStreamWaitEvent(0, eQ, 0);
    attn_mma<<<dim3(HEADS, BATCH / 128), 256, ATT_SMEM>>>(q_h, k_h, vt_h, ctx_h);
    // out projection + fuse (F = enc fp32)
    gemm_mma<2><<<gBig, 256, GEMM_SMEM>>>(ctx_h, nullptr, w_h + W_WO, bo,
        enc, nullptr, nullptr, fused_h, nullptr, BATCH, 512, 8, 512);
    // transition (K=528, ego in 9th K-chunk)
    gemm_mma<1><<<gBig, 256, GEMM_SMEM>>>(fused_h, ego_h, w_h + W_TR1, tr_b1,
        nullptr, nullptr, nullptr, h, nullptr, BATCH, 528, 9, 512);
    ln_kernel<<<BATCH/8, 256>>>(h, tr_g, tr_be, hn_h);
    gemm_mma<5><<<gBig, 256, GEMM_SMEM>>>(hn_h, nullptr, w_h + W_TR2, tr_b2,
        nullptr, nullptr, nullptr, next_state, ns_h, BATCH, 512, 8, 512);
    // quality head
    gemm_mma<3><<<gQual, 256, GEMM_SMEM>>>(ns_h, nullptr, w_h + W_Q1, q_b1,
        nullptr, q_w2, q_b2, quality, nullptr, BATCH, 512, 8, 512);
    // memory bank update
    compact_kernel<<<1, 256>>>(quality, midx, mcount);
    memupd_kernel<<<MEM, 128>>>(wm, next_state, uidx, midx, mcount, outmem);
}

// round 17
// speedup vs baseline: 1.0388x; 1.0388x over previous
#include <cuda_runtime.h>
#include <cuda_fp16.h>
#include <math.h>
#include <stdint.h>

#define BATCH 8192
#define DIM   512
#define MEM   1000
#define MEMP  1024
#define HEADS 8
#define DH    64

// ==================== helpers ====================
__device__ __forceinline__ uint32_t smem_u32(const void* p) {
    uint32_t a;
    asm("{ .reg .u64 t; cvta.to.shared.u64 t, %1; cvt.u32.u64 %0, t; }" : "=r"(a) : "l"(p));
    return a;
}
__device__ __forceinline__ void mma_f16(float* c, uint32_t a0, uint32_t a1,
                                        uint32_t a2, uint32_t a3,
                                        uint32_t b0, uint32_t b1) {
    asm volatile(
        "mma.sync.aligned.m16n8k16.row.col.f32.f16.f16.f32 "
        "{%0,%1,%2,%3}, {%4,%5,%6,%7}, {%8,%9}, {%0,%1,%2,%3};"
        : "+f"(c[0]), "+f"(c[1]), "+f"(c[2]), "+f"(c[3])
        : "r"(a0), "r"(a1), "r"(a2), "r"(a3), "r"(b0), "r"(b1));
}
__device__ __forceinline__ void ldsm_x4(uint32_t* r, uint32_t addr) {
    asm volatile("ldmatrix.sync.aligned.m8n8.x4.shared.b16 {%0,%1,%2,%3}, [%4];"
        : "=r"(r[0]), "=r"(r[1]), "=r"(r[2]), "=r"(r[3]) : "r"(addr));
}
__device__ __forceinline__ void ldsm_x2(uint32_t& r0, uint32_t& r1, uint32_t addr) {
    asm volatile("ldmatrix.sync.aligned.m8n8.x2.shared.b16 {%0,%1}, [%2];"
        : "=r"(r0), "=r"(r1) : "r"(addr));
}
__device__ __forceinline__ void cp_async16(uint32_t dst, const void* src, int srcsize) {
    asm volatile("cp.async.cg.shared.global [%0], [%1], 16, %2;"
                 :: "r"(dst), "l"(src), "r"(srcsize));
}
#define CP_COMMIT() asm volatile("cp.async.commit_group;" ::: "memory")
#define CP_WAIT(N)  asm volatile("cp.async.wait_group %0;" :: "n"(N) : "memory")

// ==================== scratch ====================
__device__ float  g_h[BATCH*DIM];
__device__ float  g_enc[BATCH*DIM];
__device__ __half g_hn_h[BATCH*DIM];
__device__ __half g_enc_h[BATCH*DIM];
__device__ __half g_q_h[BATCH*DIM];       // pre-scaled by 0.125
__device__ __half g_ctx_h[BATCH*DIM];
__device__ __half g_fused_h[BATCH*DIM];
__device__ __half g_ns_h[BATCH*DIM];
__device__ __half g_k_h[MEMP*DIM];
__device__ __half g_vt_h[DIM*MEMP];       // V^T: [d][m]
__device__ __half g_obs_h[BATCH*DIM];
__device__ __half g_ego_h[BATCH*16];
__device__ __half g_wm_h[MEMP*DIM];
__device__ __half g_w2t_h[DIM*DIM];       // enc_w2 transposed
__device__ __half g_wc_h[DIM*DIM];        // Wc = Wq * W2
__device__ float  g_bc[DIM];              // bc = Wq*b2 + bq
__device__ float  g_zero[DIM];
#define W_ENC1 0
#define W_ENC2 262144
#define W_WQ   524288
#define W_WK   786432
#define W_WV   1048576
#define W_WO   1310720
#define W_TR1  1572864
#define W_TR2  1843200
#define W_Q1   2105344
#define W_TOT  2170880
__device__ __half g_w_h[W_TOT];
__device__ int    g_midx[BATCH];
__device__ int    g_mcount;

// ==================== prep: fp32 -> fp16 ====================
struct PrepArgs {
    const float* src[12];
    __half*      dst[12];
    int          n4[12];
};
__global__ void __launch_bounds__(256) prep_kernel(PrepArgs p) {
    int seg = blockIdx.y;
    int n4 = p.n4[seg];
    const float4* s = (const float4*)p.src[seg];
    for (int i = blockIdx.x * 256 + threadIdx.x; i < n4; i += gridDim.x * 256) {
        float4 v = s[i];
        __half2 lo = __floats2half2_rn(v.x, v.y);
        __half2 hi = __floats2half2_rn(v.z, v.w);
        uint2 pk;
        pk.x = *(uint32_t*)&lo; pk.y = *(uint32_t*)&hi;
        *(uint2*)(p.dst[seg] + (size_t)i * 4) = pk;
    }
}

// transpose 512x512 fp32 -> fp16: dst[k][i] = src[i][k]
__global__ void __launch_bounds__(256) transpose_kernel(
    const float* __restrict__ src, __half* __restrict__ dst)
{
    __shared__ float tile[32][33];
    int x = blockIdx.x * 32 + threadIdx.x;
    int y0 = blockIdx.y * 32 + threadIdx.y;
    #pragma unroll
    for (int j = 0; j < 4; ++j)
        tile[threadIdx.y + j * 8][threadIdx.x] = src[(size_t)(y0 + j * 8) * 512 + x];
    __syncthreads();
    int xo = blockIdx.y * 32 + threadIdx.x;
    int yo = blockIdx.x * 32 + threadIdx.y;
    #pragma unroll
    for (int j = 0; j < 4; ++j)
        dst[(size_t)(yo + j * 8) * 512 + xo] =
            __float2half_rn(tile[threadIdx.x][threadIdx.y + j * 8]);
}

// bc[i] = bq[i] + sum_k wq[i,k] * b2[k]
__global__ void __launch_bounds__(256) bc_kernel(
    const float* __restrict__ wq, const float* __restrict__ b2,
    const float* __restrict__ bq, float* __restrict__ bc)
{
    int i = blockIdx.x * 256 + threadIdx.x;
    float s = bq[i];
    const float* wr = wq + (size_t)i * 512;
    #pragma unroll 8
    for (int k = 0; k < 512; ++k) s += wr[k] * b2[k];
    bc[i] = s;
}

// ==================== fp16 mma GEMM, 256 thr, NT=128, BK=64, 2 CTA/SM ========
// EPI: 1 relu->f32, 2 fuse->f16, 3 quality, 4 f16, 5 dual f32+f16,
//      6 f16 scaled 0.125, 7 f16 row-bias (V^T),
//      8 z-dual: z=0 like EPI5 (Cv f32 + C2v f16); z=1 W:=(half*)F, bias:=w2,
//        scaled 0.125 f16 -> C3v
#define GSH 72
#define NT  128
#define NF  4
template<int EPI>
__global__ void __launch_bounds__(256, 2) gemm_mma(
    const __half* __restrict__ A, const __half* __restrict__ A2,
    const __half* __restrict__ W, const float* __restrict__ bias,
    const float* __restrict__ F, const float* __restrict__ w2,
    const float* __restrict__ b2, void* __restrict__ Cv, void* __restrict__ C2v,
    void* __restrict__ C3v, int Mrows, int Kw, int Ktiles, int ldc)
{
    constexpr int ASZ = 128 * GSH;
    constexpr int WSZ = NT * GSH;
    extern __shared__ __half smh[];
    __half* Ah = smh;
    __half* Wh = smh + 3 * ASZ;
    const uint32_t sA = smem_u32(Ah);
    const uint32_t sW = smem_u32(Wh);

    // z-dispatch
    if (EPI == 4 && blockIdx.z) { W = (const __half*)(const void*)F; C2v = Cv; Cv = C3v; bias = w2; }
    const bool zq = (EPI == 8) && (blockIdx.z != 0);
    if (zq) { W = (const __half*)(const void*)F; bias = w2; }

    const int tid = threadIdx.x;
    const int wid = tid >> 5, lane = tid & 31;
    const int g = lane >> 2, t = lane & 3;
    const int wm = wid & 1, wn = wid >> 1;
    const int row0 = blockIdx.y * 128;
    const int col0 = blockIdx.x * NT;

    const int lane16 = lane & 15, laneHi = lane >> 4;
    const int lane8  = lane & 7,  laneK  = (lane >> 3) & 1;
    uint32_t aoff[4], boff[NF];
    #pragma unroll
    for (int mf = 0; mf < 4; ++mf)
        aoff[mf] = ((wm * 64 + mf * 16 + lane16) * GSH + laneHi * 8) * 2;
    #pragma unroll
    for (int nf = 0; nf < NF; ++nf)
        boff[nf] = ((wn * (NT / 4) + nf * 8 + lane8) * GSH + laneK * 8) * 2;

    float acc[4][NF][4];
    #pragma unroll
    for (int mf = 0; mf < 4; ++mf)
        #pragma unroll
        for (int nf = 0; nf < NF; ++nf)
            #pragma unroll
            for (int c = 0; c < 4; ++c) acc[mf][nf][c] = 0.f;

    auto load_chunk = [&](int ct, int buf) {
        const int kbase = ct * 64;
        #pragma unroll
        for (int it = 0; it < 8; ++it) {
            int vid = tid + it * 256;
            if (vid < 1024) {
                int r = vid >> 3, q = vid & 7;
                int kel = kbase + q * 8;
                int grow = row0 + r;
                const __half* src = A;
                int sz = 0;
                if (grow < Mrows) {
                    if (kel < 512) { src = A + (size_t)grow * 512 + kel; sz = 16; }
                    else if (A2 != nullptr && kel < 528) {
                        src = A2 + (size_t)grow * 16 + (kel - 512); sz = 16;
                    }
                }
                cp_async16(sA + (buf * ASZ + r * GSH + q * 8) * 2, src, sz);
            } else {
                int vid2 = vid - 1024;
                int r = vid2 >> 3, q = vid2 & 7;
                int kel = kbase + q * 8;
                const __half* src = W + (size_t)(col0 + r) * Kw + kel;
                int sz = (kel < Kw) ? 16 : 0;
                cp_async16(sW + (buf * WSZ + r * GSH + q * 8) * 2, src, sz);
            }
        }
        CP_COMMIT();
    };

    load_chunk(0, 0);
    if (Ktiles > 1) load_chunk(1, 1);

    for (int ct = 0; ct < Ktiles; ++ct) {
        const int buf = ct % 3;
        if (ct + 2 < Ktiles) load_chunk(ct + 2, (ct + 2) % 3);
        if (ct + 2 < Ktiles)      { CP_WAIT(2); }
        else if (ct + 1 < Ktiles) { CP_WAIT(1); }
        else                      { CP_WAIT(0); }
        __syncthreads();

        const uint32_t abase = sA + buf * ASZ * 2;
        const uint32_t bbase = sW + buf * WSZ * 2;
        #pragma unroll
        for (int ks = 0; ks < 4; ++ks) {
            const uint32_t kb = ks * 32;
            uint32_t af[4][4];
            #pragma unroll
            for (int mf = 0; mf < 4; ++mf)
                ldsm_x4(af[mf], abase + aoff[mf] + kb);
            #pragma unroll
            for (int nf = 0; nf < NF; ++nf) {
                uint32_t b0, b1;
                ldsm_x2(b0, b1, bbase + boff[nf] + kb);
                #pragma unroll
                for (int mf = 0; mf < 4; ++mf)
                    mma_f16(acc[mf][nf], af[mf][0], af[mf][1], af[mf][2], af[mf][3], b0, b1);
            }
        }
        __syncthreads();
    }

    if (EPI != 3) {
        #pragma unroll
        for (int mf = 0; mf < 4; ++mf) {
            #pragma unroll
            for (int r01 = 0; r01 < 2; ++r01) {
                int grow = row0 + wm * 64 + mf * 16 + g + r01 * 8;
                if (grow >= Mrows) continue;
                #pragma unroll
                for (int nf = 0; nf < NF; ++nf) {
                    int gcol = col0 + wn * (NT / 4) + nf * 8 + 2 * t;
                    float b0 = (EPI == 7) ? bias[grow] : bias[gcol];
                    float b1 = (EPI == 7) ? bias[grow] : bias[gcol + 1];
                    float v0 = acc[mf][nf][r01 * 2 + 0] + b0;
                    float v1 = acc[mf][nf][r01 * 2 + 1] + b1;
                    if (EPI == 1) { v0 = fmaxf(v0, 0.f); v1 = fmaxf(v1, 0.f); }
                    else if (EPI == 2) {
                        const float* fp = F + (size_t)grow * 512 + gcol;
                        v0 = 0.7f * fp[0] + 0.3f * v0;
                        v1 = 0.7f * fp[1] + 0.3f * v1;
                    } else if (EPI == 6) { v0 *= 0.125f; v1 *= 0.125f; }
                    size_t off = (size_t)grow * ldc + gcol;
                    if (EPI == 1) {
                        *(float2*)((float*)Cv + off) = make_float2(v0, v1);
                    } else if (EPI == 5) {
                        *(float2*)((float*)Cv + off) = make_float2(v0, v1);
                        __half2 hv = __floats2half2_rn(v0, v1);
                        *(__half2*)((__half*)C2v + off) = hv;
                    } else if (EPI == 8) {
                        if (zq) {
                            v0 *= 0.125f; v1 *= 0.125f;
                            __half2 hv = __floats2half2_rn(v0, v1);
                            *(__half2*)((__half*)C3v + off) = hv;
                        } else {
                            *(float2*)((float*)Cv + off) = make_float2(v0, v1);
                            __half2 hv = __floats2half2_rn(v0, v1);
                            *(__half2*)((__half*)C2v + off) = hv;
                        }
                    } else {
                        __half2 hv = __floats2half2_rn(v0, v1);
                        *(__half2*)((__half*)Cv + off) = hv;
                    }
                }
            }
        }
    } else {
        // quality head (NT=128, col0=0): sigmoid(b2 + sum relu(acc+b1)*w2)
        float* qpart = (float*)smh;
        __syncthreads();
        #pragma unroll
        for (int mf = 0; mf < 4; ++mf) {
            #pragma unroll
            for (int r01 = 0; r01 < 2; ++r01) {
                float s = 0.f;
                #pragma unroll
                for (int nf = 0; nf < NF; ++nf) {
                    int c = wn * (NT / 4) + nf * 8 + 2 * t;
                    float h0 = fmaxf(acc[mf][nf][r01 * 2 + 0] + bias[c], 0.f);
                    float h1 = fmaxf(acc[mf][nf][r01 * 2 + 1] + bias[c + 1], 0.f);
                    s += h0 * w2[c] + h1 * w2[c + 1];
                }
                int rl = wm * 64 + mf * 16 + r01 * 8 + g;
                qpart[rl * 17 + wn * 4 + t] = s;
            }
        }
        __syncthreads();
        if (tid < 128) {
            float s = b2[0];
            #pragma unroll
            for (int i = 0; i < 16; ++i) s += qpart[tid * 17 + i];
            ((float*)Cv)[row0 + tid] = 1.f / (1.f + expf(-s));
        }
    }
}
#define GEMM_SMEM ((3 * 128 * GSH + 3 * NT * GSH) * 2)

// ==================== fp16 mma flash attention (R15) ========================
#define AS 72
#define KVSZ (64 * AS)
#define ATT_SMEM ((128*AS + 2*KVSZ + 2*KVSZ) * 2)
__global__ void __launch_bounds__(256, 2) attn_mma(
    const __half* __restrict__ Q, const __half* __restrict__ Kb,
    const __half* __restrict__ Vt, __half* __restrict__ ctx)
{
    extern __shared__ __half smh[];
    __half* Qs = smh;
    __half* Ks = Qs + 128 * AS;
    __half* Vs = Ks + 2 * KVSZ;
    const uint32_t sQ = smem_u32(Qs);
    const uint32_t sK = smem_u32(Ks);
    const uint32_t sV = smem_u32(Vs);

    const int h = blockIdx.x;
    const int b0 = blockIdx.y * 128;
    const int tid = threadIdx.x;
    const int wid = tid >> 5, lane = tid & 31;
    const int g = lane >> 2, t = lane & 3;
    const int qr = wid * 16;

    const int lane16 = lane & 15, laneHi = lane >> 4;
    const int lane8  = lane & 7,  laneK  = (lane >> 3) & 1;
    uint32_t kvoff[8];
    #pragma unroll
    for (int nf = 0; nf < 8; ++nf)
        kvoff[nf] = ((nf * 8 + lane8) * AS + laneK * 8) * 2;

    auto load_kv = [&](int m0, int buf) {
        #pragma unroll
        for (int it = 0; it < 4; ++it) {
            int vid = tid + it * 256;
            if (vid < 512) {
                int r = vid >> 3, q = vid & 7;
                int gm = m0 + r;
                int sz = (gm < MEM) ? 16 : 0;
                cp_async16(sK + (buf * KVSZ + r * AS + q * 8) * 2,
                           Kb + (size_t)gm * 512 + h * 64 + q * 8, sz);
            } else {
                int vid2 = vid - 512;
                int r = vid2 >> 3, q = vid2 & 7;
                cp_async16(sV + (buf * KVSZ + r * AS + q * 8) * 2,
                           Vt + (size_t)(h * 64 + r) * MEMP + m0 + q * 8, 16);
            }
        }
        CP_COMMIT();
    };

    load_kv(0, 0);

    #pragma unroll
    for (int it = 0; it < 4; ++it) {
        int vid = tid + it * 256;
        int r = vid >> 3, q = vid & 7;
        uint4 v = *(const uint4*)(Q + (size_t)(b0 + r) * 512 + h * 64 + q * 8);
        *(uint4*)(Qs + r * AS + q * 8) = v;
    }
    __syncthreads();
    uint32_t qa[4][4];
    #pragma unroll
    for (int ks = 0; ks < 4; ++ks)
        ldsm_x4(qa[ks], sQ + ((qr + lane16) * AS + ks * 16 + laneHi * 8) * 2);

    float oacc[8][4];
    float rsum[2] = {0.f, 0.f};
    #pragma unroll
    for (int nf = 0; nf < 8; ++nf)
        #pragma unroll
        for (int c = 0; c < 4; ++c) oacc[nf][c] = 0.f;

    for (int ci = 0; ci < MEMP / 64; ++ci) {
        const int m0 = ci * 64;
        const int buf = ci & 1;
        if (ci + 1 < MEMP / 64) { load_kv(m0 + 64, buf ^ 1); CP_WAIT(1); }
        else                    { CP_WAIT(0); }
        __syncthreads();

        const uint32_t kbase = sK + buf * KVSZ * 2;
        const uint32_t vbase = sV + buf * KVSZ * 2;

        float sacc[8][4];
        #pragma unroll
        for (int nf = 0; nf < 8; ++nf)
            #pragma unroll
            for (int c = 0; c < 4; ++c) sacc[nf][c] = 0.f;
        #pragma unroll
        for (int ks = 0; ks < 4; ++ks) {
            const uint32_t kb = ks * 32;
            #pragma unroll
            for (int nf = 0; nf < 8; ++nf) {
                uint32_t b0, b1;
                ldsm_x2(b0, b1, kbase + kvoff[nf] + kb);
                mma_f16(sacc[nf], qa[ks][0], qa[ks][1], qa[ks][2], qa[ks][3], b0, b1);
            }
        }

        uint32_t pa[4][4];
        #pragma unroll
        for (int nf = 0; nf < 8; ++nf) {
            float p0 = 0.f, p1 = 0.f, p2 = 0.f, p3 = 0.f;
            bool in0 = (m0 + nf * 8 + 2 * t) < MEM;
            bool in1 = (m0 + nf * 8 + 2 * t + 1) < MEM;
            if (in0) { p0 = __expf(sacc[nf][0]); p2 = __expf(sacc[nf][2]); }
            if (in1) { p1 = __expf(sacc[nf][1]); p3 = __expf(sacc[nf][3]); }
            rsum[0] += p0 + p1;
            rsum[1] += p2 + p3;
            __half2 lo = __floats2half2_rn(p0, p1);
            __half2 hi = __floats2half2_rn(p2, p3);
            pa[nf >> 1][(nf & 1) * 2 + 0] = *(uint32_t*)&lo;
            pa[nf >> 1][(nf & 1) * 2 + 1] = *(uint32_t*)&hi;
        }

        #pragma unroll
        for (int ks = 0; ks < 4; ++ks) {
            const uint32_t kb = ks * 32;
            #pragma unroll
            for (int nf = 0; nf < 8; ++nf) {
                uint32_t b0, b1;
                ldsm_x2(b0, b1, vbase + kvoff[nf] + kb);
                mma_f16(oacc[nf], pa[ks][0], pa[ks][1], pa[ks][2], pa[ks][3], b0, b1);
            }
        }
        __syncthreads();
    }

    #pragma unroll
    for (int r01 = 0; r01 < 2; ++r01) {
        rsum[r01] += __shfl_xor_sync(0xffffffffu, rsum[r01], 1);
        rsum[r01] += __shfl_xor_sync(0xffffffffu, rsum[r01], 2);
    }

    #pragma unroll
    for (int r01 = 0; r01 < 2; ++r01) {
        float inv = 1.f / rsum[r01];
        int grow = b0 + qr + g + r01 * 8;
        #pragma unroll
        for (int nf = 0; nf < 8; ++nf) {
            __half2 o = __floats2half2_rn(oacc[nf][r01 * 2 + 0] * inv,
                                          oacc[nf][r01 * 2 + 1] * inv);
            *(__half2*)(ctx + (size_t)grow * 512 + h * 64 + nf * 8 + 2 * t) = o;
        }
    }
}

// ==================== LayerNorm: warp-per-row, fp32 in, fp16 out =============
__global__ void __launch_bounds__(256) ln_kernel(
    const float* __restrict__ x, const float* __restrict__ g,
    const float* __restrict__ b, __half* __restrict__ y)
{
    const int warp = threadIdx.x >> 5, lane = threadIdx.x & 31;
    const int row = blockIdx.x * 8 + warp;
    const float* xr = x + (size_t)row * 512;

    float4 v[4];
    #pragma unroll
    for (int i = 0; i < 4; ++i)
        v[i] = *(const float4*)(xr + i * 128 + lane * 4);

    float s = 0.f;
    #pragma unroll
    for (int i = 0; i < 4; ++i) s += v[i].x + v[i].y + v[i].z + v[i].w;
    #pragma unroll
    for (int o = 16; o > 0; o >>= 1) s += __shfl_xor_sync(0xffffffffu, s, o);
    float mean = s * (1.f / 512.f);

    float ss = 0.f;
    #pragma unroll
    for (int i = 0; i < 4; ++i) {
        v[i].x -= mean; v[i].y -= mean; v[i].z -= mean; v[i].w -= mean;
        ss += v[i].x * v[i].x + v[i].y * v[i].y + v[i].z * v[i].z + v[i].w * v[i].w;
    }
    #pragma unroll
    for (int o = 16; o > 0; o >>= 1) ss += __shfl_xor_sync(0xffffffffu, ss, o);
    float inv = rsqrtf(ss * (1.f / 512.f) + 1e-5f);

    #pragma unroll
    for (int i = 0; i < 4; ++i) {
        float4 gg = *(const float4*)(g + i * 128 + lane * 4);
        float4 bb = *(const float4*)(b + i * 128 + lane * 4);
        __half2 lo = __floats2half2_rn(v[i].x * inv * gg.x + bb.x,
                                       v[i].y * inv * gg.y + bb.y);
        __half2 hi = __floats2half2_rn(v[i].z * inv * gg.z + bb.z,
                                       v[i].w * inv * gg.w + bb.w);
        uint2 pk; pk.x = *(uint32_t*)&lo; pk.y = *(uint32_t*)&hi;
        *(uint2*)(y + (size_t)row * 512 + i * 128 + lane * 4) = pk;
    }
}

// ==================== mask compaction + memory EMA ====================
__global__ void __launch_bounds__(256) compact_kernel(
    const float* __restrict__ quality, int* __restrict__ midx, int* __restrict__ mcount)
{
    const int tid = threadIdx.x;
    const int base = tid * 32;
    int cnt = 0;
    for (int i = 0; i < 32; ++i) cnt += (quality[base + i] > 0.7f) ? 1 : 0;
    __shared__ int sc[256];
    __shared__ int offs[256];
    sc[tid] = cnt;
    __syncthreads();
    if (tid == 0) {
        int run = 0;
        for (int t = 0; t < 256; ++t) { offs[t] = run; run += sc[t]; }
        *mcount = run;
    }
    __syncthreads();
    int o = offs[tid];
    for (int i = 0; i < 32; ++i)
        if (quality[base + i] > 0.7f) midx[o++] = base + i;
}

__global__ void __launch_bounds__(128) memupd_kernel(
    const float* __restrict__ wm, const float* __restrict__ ns,
    const int* __restrict__ upd, const int* __restrict__ midx,
    const int* __restrict__ mcount, float* __restrict__ outmem)
{
    const int m = blockIdx.x;
    const int d = threadIdx.x * 4;
    float4 v = *(const float4*)(wm + (size_t)m * 512 + d);
    const int cnt = *mcount;
    for (int jj = 0; jj < cnt; ++jj) {
        int i = midx[jj];
        if (upd[i] == m) {
            float4 s = *(const float4*)(ns + (size_t)i * 512 + d);
            v.x = 0.9f * v.x + 0.1f * s.x;
            v.y = 0.9f * v.y + 0.1f * s.y;
            v.z = 0.9f * v.z + 0.1f * s.z;
            v.w = 0.9f * v.w + 0.1f * s.w;
        }
    }
    *(float4*)(outmem + (size_t)m * 512 + d) = v;
}

// ==================== host launcher ====================
extern "C" void kernel_launch(void* const* d_in, const int* in_sizes, int n_in,
                              void* d_out, int out_size)
{
    const float* obs    = (const float*)d_in[0];
    const float* ego    = (const float*)d_in[1];
    const float* wm     = (const float*)d_in[2];
    const float* enc_w1 = (const float*)d_in[3];
    const float* enc_b1 = (const float*)d_in[4];
    const float* enc_g  = (const float*)d_in[5];
    const float* enc_be = (const float*)d_in[6];
    const float* enc_w2 = (const float*)d_in[7];
    const float* enc_b2 = (const float*)d_in[8];
    const float* wq     = (const float*)d_in[9];
    const float* bq     = (const float*)d_in[10];
    const float* wk     = (const float*)d_in[11];
    const float* bk     = (const float*)d_in[12];
    const float* wv     = (const float*)d_in[13];
    const float* bv     = (const float*)d_in[14];
    const float* wo     = (const float*)d_in[15];
    const float* bo     = (const float*)d_in[16];
    const float* tr_w1  = (const float*)d_in[17];
    const float* tr_b1  = (const float*)d_in[18];
    const float* tr_g   = (const float*)d_in[19];
    const float* tr_be  = (const float*)d_in[20];
    const float* tr_w2  = (const float*)d_in[21];
    const float* tr_b2  = (const float*)d_in[22];
    const float* q_w1   = (const float*)d_in[23];
    const float* q_b1   = (const float*)d_in[24];
    const float* q_w2   = (const float*)d_in[25];
    const float* q_b2   = (const float*)d_in[26];
    const int*   uidx   = (const int*)d_in[27];

    float* out        = (float*)d_out;
    float* next_state = out;
    float* quality    = out + (size_t)BATCH * DIM;
    float* outmem     = quality + BATCH;

    float *h, *enc, *bc, *zero;
    __half *hn_h, *enc_h, *q_h, *ctx_h, *fused_h, *ns_h, *k_h, *vt_h;
    __half *obs_h, *ego_h, *wm_h, *w_h, *w2t_h, *wc_h;
    int *midx, *mcount;
    cudaGetSymbolAddress((void**)&h,      g_h);
    cudaGetSymbolAddress((void**)&enc,    g_enc);
    cudaGetSymbolAddress((void**)&hn_h,   g_hn_h);
    cudaGetSymbolAddress((void**)&enc_h,  g_enc_h);
    cudaGetSymbolAddress((void**)&q_h,    g_q_h);
    cudaGetSymbolAddress((void**)&ctx_h,  g_ctx_h);
    cudaGetSymbolAddress((void**)&fused_h,g_fused_h);
    cudaGetSymbolAddress((void**)&ns_h,   g_ns_h);
    cudaGetSymbolAddress((void**)&k_h,    g_k_h);
    cudaGetSymbolAddress((void**)&vt_h,   g_vt_h);
    cudaGetSymbolAddress((void**)&obs_h,  g_obs_h);
    cudaGetSymbolAddress((void**)&ego_h,  g_ego_h);
    cudaGetSymbolAddress((void**)&wm_h,   g_wm_h);
    cudaGetSymbolAddress((void**)&w_h,    g_w_h);
    cudaGetSymbolAddress((void**)&w2t_h,  g_w2t_h);
    cudaGetSymbolAddress((void**)&wc_h,   g_wc_h);
    cudaGetSymbolAddress((void**)&bc,     g_bc);
    cudaGetSymbolAddress((void**)&zero,   g_zero);
    cudaGetSymbolAddress((void**)&midx,   g_midx);
    cudaGetSymbolAddress((void**)&mcount, g_mcount);

    cudaFuncSetAttribute(gemm_mma<1>, cudaFuncAttributeMaxDynamicSharedMemorySize, GEMM_SMEM);
    cudaFuncSetAttribute(gemm_mma<2>, cudaFuncAttributeMaxDynamicSharedMemorySize, GEMM_SMEM);
    cudaFuncSetAttribute(gemm_mma<3>, cudaFuncAttributeMaxDynamicSharedMemorySize, GEMM_SMEM);
    cudaFuncSetAttribute(gemm_mma<4>, cudaFuncAttributeMaxDynamicSharedMemorySize, GEMM_SMEM);
    cudaFuncSetAttribute(gemm_mma<5>, cudaFuncAttributeMaxDynamicSharedMemorySize, GEMM_SMEM);
    cudaFuncSetAttribute(gemm_mma<7>, cudaFuncAttributeMaxDynamicSharedMemorySize, GEMM_SMEM);
    cudaFuncSetAttribute(gemm_mma<8>, cudaFuncAttributeMaxDynamicSharedMemorySize, GEMM_SMEM);
    cudaFuncSetAttribute(attn_mma,    cudaFuncAttributeMaxDynamicSharedMemorySize, ATT_SMEM);

    static cudaStream_t s1 = nullptr;
    static cudaEvent_t  eP = nullptr, eWc = nullptr, eKV = nullptr;
    if (s1 == nullptr) {
        cudaStreamCreateWithFlags(&s1, cudaStreamNonBlocking);
        cudaEventCreateWithFlags(&eP,  cudaEventDisableTiming);
        cudaEventCreateWithFlags(&eWc, cudaEventDisableTiming);
        cudaEventCreateWithFlags(&eKV, cudaEventDisableTiming);
    }

    // ---- prep: fp32 -> fp16 ----
    PrepArgs pa;
    const float* srcs[12] = {obs, ego, wm, enc_w1, enc_w2, wq, wk, wv, wo, tr_w1, tr_w2, q_w1};
    __half* dsts[12] = {obs_h, ego_h, wm_h,
                        w_h + W_ENC1, w_h + W_ENC2, w_h + W_WQ, w_h + W_WK, w_h + W_WV,
                        w_h + W_WO, w_h + W_TR1, w_h + W_TR2, w_h + W_Q1};
    int n4s[12] = {BATCH*DIM/4, BATCH*16/4, MEM*DIM/4,
                   262144/4, 262144/4, 262144/4, 262144/4, 262144/4,
                   262144/4, 270336/4, 262144/4, 65536/4};
    for (int i = 0; i < 12; ++i) { pa.src[i] = srcs[i]; pa.dst[i] = dsts[i]; pa.n4[i] = n4s[i]; }
    prep_kernel<<<dim3(512, 12), 256>>>(pa);

    dim3 gBig(4, 64), gDual(4, 64, 2), gK(4, 8), gVt(8, 4), gWc(4, 4), gQual(1, 64);

    // ---- fork: side stream — Wc path FIRST, then K/Vt ----
    cudaEventRecord(eP, 0);
    cudaStreamWaitEvent(s1, eP, 0);
    transpose_kernel<<<dim3(16, 16), dim3(32, 8), 0, s1>>>(enc_w2, w2t_h);
    bc_kernel<<<2, 256, 0, s1>>>(wq, enc_b2, bq, bc);
    gemm_mma<4><<<gWc, 256, GEMM_SMEM, s1>>>(w_h + W_WQ, nullptr, w2t_h, zero,
        nullptr, nullptr, nullptr, wc_h, nullptr, nullptr, 512, 512, 8, 512);
    cudaEventRecord(eWc, s1);
    gemm_mma<4><<<gK, 256, GEMM_SMEM, s1>>>(wm_h, nullptr, w_h + W_WK, bk,
        nullptr, nullptr, nullptr, k_h, nullptr, nullptr, MEM, 512, 8, 512);
    gemm_mma<7><<<gVt, 256, GEMM_SMEM, s1>>>(w_h + W_WV, nullptr, wm_h, bv,
        nullptr, nullptr, nullptr, vt_h, nullptr, nullptr, 512, 512, 8, MEMP);
    cudaEventRecord(eKV, s1);

    // ---- main chain ----
    gemm_mma<1><<<gBig, 256, GEMM_SMEM>>>(obs_h, nullptr, w_h + W_ENC1, enc_b1,
        nullptr, nullptr, nullptr, h, nullptr, nullptr, BATCH, 512, 8, 512);
    ln_kernel<<<BATCH/8, 256>>>(h, enc_g, enc_be, hn_h);
    // dual: z=0 enc (f32+f16) via W2; z=1 q via Wc (+bc, x0.125)
    cudaStreamWaitEvent(0, eWc, 0);
    gemm_mma<8><<<gDual, 256, GEMM_SMEM>>>(hn_h, nullptr, w_h + W_ENC2, enc_b2,
        (const float*)(const void*)wc_h, bc, nullptr, enc, enc_h, q_h, BATCH, 512, 8, 512);
    // join K/Vt before attention
    cudaStreamWaitEvent(0, eKV, 0);
    attn_mma<<<dim3(HEADS, BATCH / 128), 256, ATT_SMEM>>>(q_h, k_h, vt_h, ctx_h);
    // out projection + fuse (F = enc fp32)
    gemm_mma<2><<<gBig, 256, GEMM_SMEM>>>(ctx_h, nullptr, w_h + W_WO, bo,
        enc, nullptr, nullptr, fused_h, nullptr, nullptr, BATCH, 512, 8, 512);
    // transition (K=528, ego in 9th K-chunk)
    gemm_mma<1><<<gBig, 256, GEMM_SMEM>>>(fused_h, ego_h, w_h + W_TR1, tr_b1,
        nullptr, nullptr, nullptr, h, nullptr, nullptr, BATCH, 528, 9, 512);
    ln_kernel<<<BATCH/8, 256>>>(h, tr_g, tr_be, hn_h);
    gemm_mma<5><<<gBig, 256, GEMM_SMEM>>>(hn_h, nullptr, w_h + W_TR2, tr_b2,
        nullptr, nullptr, nullptr, next_state, ns_h, nullptr, BATCH, 512, 8, 512);
    // quality head
    gemm_mma<3><<<gQual, 256, GEMM_SMEM>>>(ns_h, nullptr, w_h + W_Q1, q_b1,
        nullptr, q_w2, q_b2, quality, nullptr, nullptr, BATCH, 512, 8, 512);
    // memory bank update
    compact_kernel<<<1, 256>>>(quality, midx, mcount);
    memupd_kernel<<<MEM, 128>>>(wm, next_state, uidx, midx, mcount, outmem);
}